// round 7
// baseline (speedup 1.0000x reference)
#include <cuda_runtime.h>
#include <math_constants.h>

#define N_ROWS  128
#define IN_DIM  1024
#define OUT_DIM 1024

#define TM 32
#define TN 32
#define KC 64
#define LDSTR 68        // 68 % 32 == 4 -> 8 consecutive rows hit 32 distinct banks
#define KSPLIT 2
#define KHALF  (IN_DIM / KSPLIT)   // 512
#define NCHUNK (KHALF / KC)        // 8

// Packed fp32 pair add (sm_103a f32x2 family: add/mul/fma only — no packed max)
__device__ __forceinline__ void add2(float a0, float a1, float b0, float b1,
                                     float& s0, float& s1) {
    unsigned long long ra, rb, rc;
    asm("mov.b64 %0, {%1, %2};" : "=l"(ra) : "f"(a0), "f"(a1));
    asm("mov.b64 %0, {%1, %2};" : "=l"(rb) : "f"(b0), "f"(b1));
    asm("add.rn.f32x2 %0, %1, %2;" : "=l"(rc) : "l"(ra), "l"(rb));
    asm("mov.b64 {%0, %1}, %2;" : "=f"(s0), "=f"(s1) : "l"(rc));
}

__device__ __forceinline__ float max4acc(float acc, float s0, float s1, float s2, float s3) {
    return fmaxf(acc, fmaxf(fmaxf(s0, s1), fmaxf(s2, s3)));
}

// Scratch for split-K partials (device global: allocation rules forbid malloc)
__device__ float g_partial[KSPLIT * N_ROWS * OUT_DIM];

__global__ __launch_bounds__(256, 2)
void tropical_main_kernel(const float* __restrict__ x,
                          const float* __restrict__ w) {
    __shared__ float xs[2][TM * LDSTR];
    __shared__ float ws[2][TN * LDSTR];

    const int tid  = threadIdx.x;
    const int lane = tid & 31;
    const int warp = tid >> 5;            // 0..7
    const int ln   = lane >> 3;           // 0..3  n within warp
    const int lo   = lane & 7;            // 0..7  o within warp
    const int wn   = (warp >> 1) * 8;     // 0,8,16,24
    const int wo   = (warp & 1) * 16;     // 0,16

    const int o0    = blockIdx.x * TN;
    const int n0    = blockIdx.y * TM;
    const int kz    = blockIdx.z;         // 0..1
    const int kbase = kz * KHALF;

    // Global staging: 512 float4 per array per chunk, 256 threads x 2 each.
    const int f0 = tid,       r0 = f0 >> 4, c0 = f0 & 15;
    const int f1 = tid + 256, r1 = f1 >> 4, c1 = f1 & 15;

    const float* xg = x + n0 * IN_DIM + kbase;
    const float* wg = w + o0 * IN_DIM + kbase;

    float4 px0 = *(const float4*)&xg[r0 * IN_DIM + c0 * 4];
    float4 px1 = *(const float4*)&xg[r1 * IN_DIM + c1 * 4];
    float4 pw0 = *(const float4*)&wg[r0 * IN_DIM + c0 * 4];
    float4 pw1 = *(const float4*)&wg[r1 * IN_DIM + c1 * 4];

    float acc00 = -CUDART_INF_F, acc01 = -CUDART_INF_F;
    float acc10 = -CUDART_INF_F, acc11 = -CUDART_INF_F;

    *(float4*)&xs[0][r0 * LDSTR + c0 * 4] = px0;
    *(float4*)&xs[0][r1 * LDSTR + c1 * 4] = px1;
    *(float4*)&ws[0][r0 * LDSTR + c0 * 4] = pw0;
    *(float4*)&ws[0][r1 * LDSTR + c1 * 4] = pw1;
    __syncthreads();

    for (int t = 0; t < NCHUNK; ++t) {
        const int buf = t & 1;

        if (t < NCHUNK - 1) {
            const int k0 = (t + 1) * KC;
            px0 = *(const float4*)&xg[r0 * IN_DIM + k0 + c0 * 4];
            px1 = *(const float4*)&xg[r1 * IN_DIM + k0 + c1 * 4];
            pw0 = *(const float4*)&wg[r0 * IN_DIM + k0 + c0 * 4];
            pw1 = *(const float4*)&wg[r1 * IN_DIM + k0 + c1 * 4];
        }

        const float* xb = xs[buf];
        const float* wb = ws[buf];

        #pragma unroll
        for (int kk = 0; kk < KC; kk += 4) {
            // 4 x LDS.128, each one conflict-free wavefront
            float4 xv0 = *(const float4*)&xb[(wn +     ln) * LDSTR + kk];
            float4 xv1 = *(const float4*)&xb[(wn + 4 + ln) * LDSTR + kk];
            float4 wv0 = *(const float4*)&wb[(wo +     lo) * LDSTR + kk];
            float4 wv1 = *(const float4*)&wb[(wo + 8 + lo) * LDSTR + kk];

            float s0, s1, s2, s3;

            add2(xv0.x, xv0.y, wv0.x, wv0.y, s0, s1);
            add2(xv0.z, xv0.w, wv0.z, wv0.w, s2, s3);
            acc00 = max4acc(acc00, s0, s1, s2, s3);

            add2(xv0.x, xv0.y, wv1.x, wv1.y, s0, s1);
            add2(xv0.z, xv0.w, wv1.z, wv1.w, s2, s3);
            acc01 = max4acc(acc01, s0, s1, s2, s3);

            add2(xv1.x, xv1.y, wv0.x, wv0.y, s0, s1);
            add2(xv1.z, xv1.w, wv0.z, wv0.w, s2, s3);
            acc10 = max4acc(acc10, s0, s1, s2, s3);

            add2(xv1.x, xv1.y, wv1.x, wv1.y, s0, s1);
            add2(xv1.z, xv1.w, wv1.z, wv1.w, s2, s3);
            acc11 = max4acc(acc11, s0, s1, s2, s3);
        }

        if (t < NCHUNK - 1) {
            const int nb = buf ^ 1;
            *(float4*)&xs[nb][r0 * LDSTR + c0 * 4] = px0;
            *(float4*)&xs[nb][r1 * LDSTR + c1 * 4] = px1;
            *(float4*)&ws[nb][r0 * LDSTR + c0 * 4] = pw0;
            *(float4*)&ws[nb][r1 * LDSTR + c1 * 4] = pw1;
        }
        __syncthreads();
    }

    const int n_a = n0 + wn + ln;
    const int n_b = n_a + 4;
    const int o_a = o0 + wo + lo;
    const int o_b = o_a + 8;
    float* part = g_partial + kz * (N_ROWS * OUT_DIM);

    part[n_a * OUT_DIM + o_a] = acc00;
    part[n_a * OUT_DIM + o_b] = acc01;
    part[n_b * OUT_DIM + o_a] = acc10;
    part[n_b * OUT_DIM + o_b] = acc11;
}

__global__ __launch_bounds__(256, 1)
void tropical_combine_kernel(const float* __restrict__ bias,
                             float* __restrict__ out) {
    const int i = (blockIdx.x * 256 + threadIdx.x) * 4;   // 131072 elems total
    float4 a  = *(const float4*)&g_partial[i];
    float4 b  = *(const float4*)&g_partial[N_ROWS * OUT_DIM + i];
    float4 bs = *(const float4*)&bias[i & (OUT_DIM - 1)];
    float4 r;
    r.x = fmaxf(a.x, b.x) + bs.x;
    r.y = fmaxf(a.y, b.y) + bs.y;
    r.z = fmaxf(a.z, b.z) + bs.z;
    r.w = fmaxf(a.w, b.w) + bs.w;
    *(float4*)&out[i] = r;
}

extern "C" void kernel_launch(void* const* d_in, const int* in_sizes, int n_in,
                              void* d_out, int out_size) {
    const float* x    = (const float*)d_in[0];   // [128, 1024]
    const float* wgt  = (const float*)d_in[1];   // [1024, 1024]
    const float* bias = (const float*)d_in[2];   // [1024]
    float* out        = (float*)d_out;           // [128, 1024]

    dim3 grid(OUT_DIM / TN, N_ROWS / TM, KSPLIT);   // (32, 4, 2) = 256 blocks
    tropical_main_kernel<<<grid, 256>>>(x, wgt);

    dim3 cgrid((N_ROWS * OUT_DIM / 4) / 256);       // 128 blocks
    tropical_combine_kernel<<<cgrid, 256>>>(bias, out);
}